// round 10
// baseline (speedup 1.0000x reference)
#include <cuda_runtime.h>
#include <cuda_bf16.h>
#include <math.h>
#include <stdint.h>

// ---------------- problem constants ----------------
#define Bn 8
#define Hn 192
#define Wn 192
#define Cn 64
#define NPIX (Bn*Hn*Wn)          // 294912
#define CV 81
#define CIN0 209
#define P0 216                    // padded channel stride (27 * 8)
#define FLOW_SCALE 271.52900393598527f
#define BN_EPS 1e-3f

// ---------------- scratch ----------------
__device__ float g_bufA[(size_t)NPIX * P0 + 256];
__device__ float g_bufB[(size_t)NPIX * P0 + 256];
__device__ float g_dw0pad[9 * P0];
__device__ __nv_bfloat16 g_w0hi[224 * 128];
__device__ __nv_bfloat16 g_w0lo[224 * 128];
__device__ __nv_bfloat16 g_w1hi[128 * 64];
__device__ __nv_bfloat16 g_w1lo[128 * 64];

__device__ __forceinline__ float mish(float x) {
    float sp = fmaxf(x, 0.f) + log1pf(expf(-fabsf(x)));
    return x * tanhf(sp);
}

// ---------------- packed f32x2 helpers (layers 2,3 GEMM) ----------------
__device__ __forceinline__ unsigned long long pack2(float x, float y) {
    unsigned long long r;
    asm("mov.b64 %0, {%1, %2};" : "=l"(r) : "f"(x), "f"(y));
    return r;
}
__device__ __forceinline__ void unpack2(unsigned long long v, float& x, float& y) {
    asm("mov.b64 {%0, %1}, %2;" : "=f"(x), "=f"(y) : "l"(v));
}
__device__ __forceinline__ void ffma2(unsigned long long& c, unsigned long long a, unsigned long long b) {
    asm("fma.rn.f32x2 %0, %1, %2, %0;" : "+l"(c) : "l"(a), "l"(b));
}

// ---------------- mma helpers ----------------
__device__ __forceinline__ uint32_t smem_u32(const void* p) {
    uint32_t a;
    asm("{ .reg .u64 t; cvta.to.shared.u64 t, %1; cvt.u32.u64 %0, t; }" : "=r"(a) : "l"(p));
    return a;
}
__device__ __forceinline__ void ldmx4(uint32_t* r, uint32_t addr) {
    asm volatile("ldmatrix.sync.aligned.m8n8.x4.shared.b16 {%0,%1,%2,%3}, [%4];"
                 : "=r"(r[0]), "=r"(r[1]), "=r"(r[2]), "=r"(r[3]) : "r"(addr));
}
__device__ __forceinline__ void ldmx4t(uint32_t* r, uint32_t addr) {
    asm volatile("ldmatrix.sync.aligned.m8n8.x4.trans.shared.b16 {%0,%1,%2,%3}, [%4];"
                 : "=r"(r[0]), "=r"(r[1]), "=r"(r[2]), "=r"(r[3]) : "r"(addr));
}
__device__ __forceinline__ void mma_bf16(float* d, const uint32_t* a, uint32_t b0, uint32_t b1) {
    asm volatile("mma.sync.aligned.m16n8k16.row.col.f32.bf16.bf16.f32 "
                 "{%0,%1,%2,%3}, {%4,%5,%6,%7}, {%8,%9}, {%0,%1,%2,%3};"
                 : "+f"(d[0]), "+f"(d[1]), "+f"(d[2]), "+f"(d[3])
                 : "r"(a[0]), "r"(a[1]), "r"(a[2]), "r"(a[3]), "r"(b0), "r"(b1));
}
__device__ __forceinline__ void split_bf16(float v, uint16_t& hi, uint16_t& lo) {
    __nv_bfloat16 h = __float2bfloat16(v);
    float r = v - __bfloat162float(h);
    __nv_bfloat16 l = __float2bfloat16(r);
    hi = *(uint16_t*)&h;
    lo = *(uint16_t*)&l;
}

// ---------------- kernel 0: prep weights ----------------
__global__ void prep_kernel(const float* __restrict__ dw0, const float* __restrict__ pw0,
                            const float* __restrict__ pw1)
{
    int idx = blockIdx.x * blockDim.x + threadIdx.x;
    if (idx < 9 * P0) {
        int c = idx % P0;
        int k = idx / P0;
        g_dw0pad[idx] = (c < CIN0) ? dw0[k * CIN0 + c] : 0.f;
    }
    if (idx < 224 * 128) {
        int n = idx & 127;
        int k = idx >> 7;
        float v = (k < CIN0) ? pw0[k * 128 + n] : 0.f;
        uint16_t hi, lo;
        split_bf16(v, hi, lo);
        *(uint16_t*)&g_w0hi[idx] = hi;
        *(uint16_t*)&g_w0lo[idx] = lo;
    }
    if (idx < 128 * 64) {
        uint16_t hi, lo;
        split_bf16(pw1[idx], hi, lo);
        *(uint16_t*)&g_w1hi[idx] = hi;
        *(uint16_t*)&g_w1lo[idx] = lo;
    }
}

// ---------------- kernel 1: cost volume (+ concat fold in DXB==0 pass) ----------------
template<int DXB, int NDX>
__global__ __launch_bounds__(128)
void cost_kernel(const float* __restrict__ prv, const float* __restrict__ nxt,
                 float* __restrict__ x0)
{
    __shared__ float sbuf[16 * 661];
    __shared__ float sout[NDX * 9 * 257];

    const int tid  = threadIdx.x;
    const int lane = tid & 31;
    const int wp   = tid >> 5;
    const int bx = blockIdx.x, by = blockIdx.y, b = blockIdx.z;

    const int x    = bx * 32 + lane;
    const int y0   = by * 8 + wp * 2;
    const size_t pix0 = (size_t)(b * Hn + y0) * Wn + x;
    const size_t pix1 = pix0 + Wn;

    float acc0[NDX * 9], acc1[NDX * 9];
#pragma unroll
    for (int t = 0; t < NDX * 9; t++) { acc0[t] = 0.f; acc1[t] = 0.f; }

#pragma unroll 1
    for (int chp = 0; chp < 4; chp++) {
        __syncthreads();
#pragma unroll 4
        for (int k = 0; k < 80; k++) {
            int i = tid + k * 128;
            int c = i & 15;
            int rest = i >> 4;
            int xs = rest % 40;
            int r  = rest / 40;
            int gy = by * 8 + r - 4;
            int gx = bx * 32 + xs - 4;
            float v = 0.f;
            if (gy >= 0 && gy < Hn && gx >= 0 && gx < Wn)
                v = nxt[((size_t)(b * Hn + gy) * Wn + gx) * Cn + chp * 16 + c];
            sbuf[c * 661 + r * 41 + xs] = v;
        }
        __syncthreads();

#pragma unroll 1
        for (int c4 = 0; c4 < 4; c4++) {
            float4 pa = *(const float4*)(prv + pix0 * Cn + chp * 16 + c4 * 4);
            float4 pb = *(const float4*)(prv + pix1 * Cn + chp * 16 + c4 * 4);
            float pav[4] = {pa.x, pa.y, pa.z, pa.w};
            float pbv[4] = {pb.x, pb.y, pb.z, pb.w};
#pragma unroll
            for (int cc = 0; cc < 4; cc++) {
                const float* splane = &sbuf[(c4 * 4 + cc) * 661];
#pragma unroll
                for (int rr = 0; rr < 10; rr++) {
                    const float* q = &splane[(wp * 2 + rr) * 41 + lane + DXB];
#pragma unroll
                    for (int d = 0; d < NDX; d++) {
                        float qv = q[d];
                        if (rr < 9)  acc0[rr * NDX + d]       = fmaf(pav[cc], qv, acc0[rr * NDX + d]);
                        if (rr >= 1) acc1[(rr - 1) * NDX + d] = fmaf(pbv[cc], qv, acc1[(rr - 1) * NDX + d]);
                    }
                }
            }
        }
    }

    __syncthreads();
    const int pl0 = wp * 64 + lane;
#pragma unroll
    for (int t = 0; t < NDX * 9; t++) {
        float v0 = acc0[t] * (1.f / 64.f); v0 = (v0 > 0.f) ? v0 : 0.1f * v0;
        float v1 = acc1[t] * (1.f / 64.f); v1 = (v1 > 0.f) ? v1 : 0.1f * v1;
        sout[t * 257 + pl0]      = v0;
        sout[t * 257 + pl0 + 32] = v1;
    }
    __syncthreads();

    const int TOT = 256 * NDX * 9;
    for (int i = tid; i < TOT; i += 128) {
        int px = i / (NDX * 9);
        int t  = i % (NDX * 9);
        int dy = t / NDX, d = t % NDX;
        int yl = px >> 5, xx = px & 31;
        size_t pix = (size_t)(b * Hn + by * 8 + yl) * Wn + bx * 32 + xx;
        x0[pix * P0 + dy * 9 + DXB + d] = sout[t * 257 + px];
    }

    if (DXB == 0) {
        for (int j = tid; j < 256 * 64; j += 128) {
            int px = j >> 6, c = j & 63;
            int yl = px >> 5, xx = px & 31;
            size_t pix = (size_t)(b * Hn + by * 8 + yl) * Wn + bx * 32 + xx;
            x0[pix * P0 + CV + c]      = prv[pix * Cn + c];
            x0[pix * P0 + CV + 64 + c] = nxt[pix * Cn + c];
            if (c >= 57) x0[pix * P0 + 152 + c] = 0.f;   // 209..215
        }
    }
}

// ---------------- kernel 2: depthwise 3x3, float4 channels, 4 y-outputs/thread ----------------
template<int QUADS, int STRIDE, int WSTRIDE>
__global__ __launch_bounds__(256)
void dw4y_kernel(const float* __restrict__ X, const float* __restrict__ Wd,
                 float* __restrict__ Y)
{
    int idx = blockIdx.x * blockDim.x + threadIdx.x;
    if (idx >= (NPIX / 4) * QUADS) return;
    int q    = idx % QUADS;
    int rest = idx / QUADS;
    int w    = rest % Wn;
    int rest2 = rest / Wn;
    int hg   = rest2 % (Hn / 4);
    int b    = rest2 / (Hn / 4);
    const int h0 = hg * 4;

    float4 wv[9];
#pragma unroll
    for (int t = 0; t < 9; t++)
        wv[t] = *(const float4*)(Wd + t * WSTRIDE + q * 4);

    float4 acc[4];
#pragma unroll
    for (int m = 0; m < 4; m++) acc[m] = make_float4(0.f, 0.f, 0.f, 0.f);

    const bool wl = (w - 1 >= 0), wr = (w + 1 < Wn);

#pragma unroll
    for (int r = 0; r < 6; r++) {
        int hh = h0 + r - 1;
        if (hh < 0 || hh >= Hn) continue;
        const float* rowp = X + ((size_t)((b * Hn + hh) * Wn + w)) * STRIDE + q * 4;
#pragma unroll
        for (int kx = 0; kx < 3; kx++) {
            if (kx == 0 && !wl) continue;
            if (kx == 2 && !wr) continue;
            float4 xv = *(const float4*)(rowp + (kx - 1) * STRIDE);
#pragma unroll
            for (int m = 0; m < 4; m++) {
                int ky = r - m;
                if (ky < 0 || ky > 2) continue;
                float4 wq = wv[ky * 3 + kx];
                acc[m].x = fmaf(xv.x, wq.x, acc[m].x);
                acc[m].y = fmaf(xv.y, wq.y, acc[m].y);
                acc[m].z = fmaf(xv.z, wq.z, acc[m].z);
                acc[m].w = fmaf(xv.w, wq.w, acc[m].w);
            }
        }
    }

#pragma unroll
    for (int m = 0; m < 4; m++) {
        size_t pix = (size_t)((b * Hn + h0 + m) * Wn + w);
        *(float4*)(Y + pix * STRIDE + q * 4) = acc[m];
    }
}

// ---------------- kernel 3a: bf16-split HMMA GEMM + bias + mish (layers 0,1) ----------------
// X:[NPIX,LDX] fp32, W hi/lo: [KTILES*16, N_] bf16 (pad rows zero), Y:[NPIX,N_]
// Block: 128 px, 256 threads = 8 warps (4 m x 2 n). Warp tile 32 x (N_/2).
template<int N_, int KTILES, int LDX>
__global__ __launch_bounds__(256, 2)
void mma_gemm_mish(const float* __restrict__ X,
                   const __nv_bfloat16* __restrict__ Whi,
                   const __nv_bfloat16* __restrict__ Wlo,
                   const float* __restrict__ bias,
                   float* __restrict__ Y)
{
    constexpr int XP = 24;          // bf16 pitch for X tiles
    constexpr int WP = N_ + 8;      // bf16 pitch for W tiles
    constexpr int WN = N_ / 2;      // warp n-extent
    constexpr int NPAIRS = WN / 16; // ldmatrix.x4.trans pairs per warp

    __shared__ __nv_bfloat16 Xs[2][2][128 * XP];
    __shared__ __nv_bfloat16 Ws[2][2][16 * WP];

    const int tid  = threadIdx.x;
    const int lane = tid & 31;
    const int warp = tid >> 5;
    const int wm   = warp >> 1;     // 0..3
    const int wn   = warp & 1;      // 0..1
    const int px0  = blockIdx.x * 128;

    float acc[2][2 * NPAIRS][4];
#pragma unroll
    for (int i = 0; i < 2; i++)
#pragma unroll
        for (int j = 0; j < 2 * NPAIRS; j++)
#pragma unroll
            for (int k = 0; k < 4; k++) acc[i][j][k] = 0.f;

    // stage lambda: ktile kt -> buffer b
    const int xrow  = tid >> 1;
    const int xhalf = tid & 1;
    auto stage = [&](int kt, int b) {
        // X: 128 rows x 16 ch fp32 -> bf16 hi/lo
        const float* src = X + (size_t)(px0 + xrow) * LDX + kt * 16 + xhalf * 8;
        float4 v0 = *(const float4*)(src);
        float4 v1 = *(const float4*)(src + 4);
        float f[8] = {v0.x, v0.y, v0.z, v0.w, v1.x, v1.y, v1.z, v1.w};
        uint16_t hb[8], lb[8];
#pragma unroll
        for (int j = 0; j < 8; j++) split_bf16(f[j], hb[j], lb[j]);
        uint32_t doff = xrow * XP + xhalf * 8;
        uint4 hu, lu;
        hu.x = hb[0] | ((uint32_t)hb[1] << 16); hu.y = hb[2] | ((uint32_t)hb[3] << 16);
        hu.z = hb[4] | ((uint32_t)hb[5] << 16); hu.w = hb[6] | ((uint32_t)hb[7] << 16);
        lu.x = lb[0] | ((uint32_t)lb[1] << 16); lu.y = lb[2] | ((uint32_t)lb[3] << 16);
        lu.z = lb[4] | ((uint32_t)lb[5] << 16); lu.w = lb[6] | ((uint32_t)lb[7] << 16);
        *(uint4*)&Xs[b][0][doff] = hu;
        *(uint4*)&Xs[b][1][doff] = lu;
        // W: 16 rows x N_ bf16 (hi + lo)
        if (tid < 2 * N_) {
            int wrow = tid / (N_ / 8);
            int wcol = (tid % (N_ / 8)) * 8;
            size_t goff = (size_t)(kt * 16 + wrow) * N_ + wcol;
            *(uint4*)&Ws[b][0][wrow * WP + wcol] = *(const uint4*)&Whi[goff];
            *(uint4*)&Ws[b][1][wrow * WP + wcol] = *(const uint4*)&Wlo[goff];
        }
    };

    stage(0, 0);
    __syncthreads();

#pragma unroll 1
    for (int kt = 0; kt < KTILES; kt++) {
        const int b = kt & 1;
        if (kt + 1 < KTILES) stage(kt + 1, (kt + 1) & 1);

        // A fragments (hi, lo) for both m-subtiles
        uint32_t a[2][2][4];
#pragma unroll
        for (int mi = 0; mi < 2; mi++) {
            uint32_t aoff = ((wm * 32 + mi * 16 + (lane & 15)) * XP + (lane >> 4) * 8) * 2;
#pragma unroll
            for (int s = 0; s < 2; s++)
                ldmx4(a[mi][s], smem_u32(&Xs[b][s][0]) + aoff);
        }
#pragma unroll
        for (int np = 0; np < NPAIRS; np++) {
            uint32_t boff = (((lane & 15)) * WP + wn * WN + np * 16 + (lane >> 4) * 8) * 2;
            uint32_t bh[4], bl[4];
            ldmx4t(bh, smem_u32(&Ws[b][0][0]) + boff);
            ldmx4t(bl, smem_u32(&Ws[b][1][0]) + boff);
#pragma unroll
            for (int mi = 0; mi < 2; mi++) {
                mma_bf16(acc[mi][2 * np],     a[mi][0], bh[0], bh[1]);
                mma_bf16(acc[mi][2 * np],     a[mi][1], bh[0], bh[1]);
                mma_bf16(acc[mi][2 * np],     a[mi][0], bl[0], bl[1]);
                mma_bf16(acc[mi][2 * np + 1], a[mi][0], bh[2], bh[3]);
                mma_bf16(acc[mi][2 * np + 1], a[mi][1], bh[2], bh[3]);
                mma_bf16(acc[mi][2 * np + 1], a[mi][0], bl[2], bl[3]);
            }
        }
        __syncthreads();
    }

    // epilogue
    const int r  = lane >> 2;
    const int c2 = (lane & 3) * 2;
#pragma unroll
    for (int mi = 0; mi < 2; mi++) {
#pragma unroll
        for (int nt = 0; nt < 2 * NPAIRS; nt++) {
            int col = wn * WN + nt * 8 + c2;
            float bb0 = __ldg(bias + col), bb1 = __ldg(bias + col + 1);
            size_t row0 = (size_t)(px0 + wm * 32 + mi * 16 + r);
            float2 o0, o1;
            o0.x = mish(acc[mi][nt][0] + bb0);
            o0.y = mish(acc[mi][nt][1] + bb1);
            o1.x = mish(acc[mi][nt][2] + bb0);
            o1.y = mish(acc[mi][nt][3] + bb1);
            *(float2*)&Y[row0 * N_ + col]       = o0;
            *(float2*)&Y[(row0 + 8) * N_ + col] = o1;
        }
    }
}

// ---------------- kernel 3b: SGEMM (f32x2) + bias + mish (layers 2,3) ----------------
template<int BN_, int TN_, int KTILES>
__global__ __launch_bounds__(256)
void sgemm_mish(const float* __restrict__ X, int ldX,
                const float* __restrict__ Wp,
                const float* __restrict__ bias,
                float* __restrict__ Y)
{
    __shared__ float As[2][8][128];
    __shared__ float Bs[2][8][BN_];

    const int tid = threadIdx.x;
    const int px0 = blockIdx.x * 128;

    const int arow = tid >> 1;
    const int acol = (tid & 1) * 4;
    const float* aptr = X + (size_t)(px0 + arow) * ldX + acol;

    constexpr int BLOADERS = BN_ * 2;
    const int brow = tid / (BN_ / 4);
    const int bcol = (tid % (BN_ / 4)) * 4;
    const float* bptr = Wp + (size_t)brow * BN_ + bcol;

    const int tcx = tid & 15;
    const int tcy = tid >> 4;

    unsigned long long accp[4][TN_];
#pragma unroll
    for (int j = 0; j < 4; j++)
#pragma unroll
        for (int n = 0; n < TN_; n++) accp[j][n] = 0ULL;

    float4 av = *(const float4*)aptr;
    float4 bv;
    if (tid < BLOADERS) bv = *(const float4*)bptr;

    As[0][acol + 0][arow] = av.x;
    As[0][acol + 1][arow] = av.y;
    As[0][acol + 2][arow] = av.z;
    As[0][acol + 3][arow] = av.w;
    if (tid < BLOADERS) *(float4*)&Bs[0][brow][bcol] = bv;
    __syncthreads();

#pragma unroll 1
    for (int kt = 0; kt < KTILES; kt++) {
        const int buf = kt & 1;
        if (kt + 1 < KTILES) {
            av = *(const float4*)(aptr + (kt + 1) * 8);
            if (tid < BLOADERS) bv = *(const float4*)(bptr + (size_t)(kt + 1) * 8 * BN_);
        }
#pragma unroll
        for (int kk = 0; kk < 8; kk++) {
            float4 a0 = *(const float4*)&As[buf][kk][tcy * 4];
            float4 a1 = *(const float4*)&As[buf][kk][tcy * 4 + 64];
            unsigned long long ap[4];
            ap[0] = pack2(a0.x, a0.y);
            ap[1] = pack2(a0.z, a0.w);
            ap[2] = pack2(a1.x, a1.y);
            ap[3] = pack2(a1.z, a1.w);

            float br[TN_];
            if constexpr (TN_ == 2) {
                float2 b0 = *(const float2*)&Bs[buf][kk][tcx * 2];
                br[0] = b0.x; br[1] = b0.y;
            } else {
                br[0] = Bs[buf][kk][tcx];
            }
            unsigned long long bd[TN_];
#pragma unroll
            for (int n = 0; n < TN_; n++) bd[n] = pack2(br[n], br[n]);
#pragma unroll
            for (int j = 0; j < 4; j++)
#pragma unroll
                for (int n = 0; n < TN_; n++)
                    ffma2(accp[j][n], ap[j], bd[n]);
        }
        if (kt + 1 < KTILES) {
            const int nb = buf ^ 1;
            As[nb][acol + 0][arow] = av.x;
            As[nb][acol + 1][arow] = av.y;
            As[nb][acol + 2][arow] = av.z;
            As[nb][acol + 3][arow] = av.w;
            if (tid < BLOADERS) *(float4*)&Bs[nb][brow][bcol] = bv;
        }
        __syncthreads();
    }

    float acc[8][TN_];
#pragma unroll
    for (int j = 0; j < 4; j++)
#pragma unroll
        for (int n = 0; n < TN_; n++)
            unpack2(accp[j][n], acc[2 * j][n], acc[2 * j + 1][n]);

    float bb[TN_];
    if constexpr (TN_ == 2) {
        float2 t0 = *(const float2*)&bias[tcx * 2];
        bb[0] = t0.x; bb[1] = t0.y;
    } else {
        bb[0] = bias[tcx];
    }

#pragma unroll
    for (int g = 0; g < 2; g++) {
#pragma unroll
        for (int m = 0; m < 4; m++) {
            int px = px0 + tcy * 4 + m + g * 64;
            float* yr = Y + (size_t)px * BN_;
            float ov[TN_];
#pragma unroll
            for (int n = 0; n < TN_; n++) ov[n] = mish(acc[g * 4 + m][n] + bb[n]);
            if constexpr (TN_ == 2) {
                *(float2*)&yr[tcx * 2] = make_float2(ov[0], ov[1]);
            } else {
                yr[tcx] = ov[0];
            }
        }
    }
}

// ---------------- kernel 4: BN + 3x3 flow conv + scale ----------------
__global__ void final_kernel(const float* __restrict__ X,
                             const float* __restrict__ gamma, const float* __restrict__ beta,
                             const float* __restrict__ mean,  const float* __restrict__ var,
                             const float* __restrict__ Wf, float* __restrict__ out)
{
    int pix = blockIdx.x * blockDim.x + threadIdx.x;
    if (pix >= NPIX) return;
    int w = pix % Wn;
    int h = (pix / Wn) % Hn;
    int b = pix / (Wn * Hn);

    float sc[16], sh[16];
#pragma unroll
    for (int c = 0; c < 16; c++) {
        float s = gamma[c] * rsqrtf(var[c] + BN_EPS);
        sc[c] = s;
        sh[c] = beta[c] - mean[c] * s;
    }

    float f0 = 0.f, f1 = 0.f;
#pragma unroll
    for (int ky = 0; ky < 3; ky++) {
        int hh = h + ky - 1;
        if (hh < 0 || hh >= Hn) continue;
#pragma unroll
        for (int kx = 0; kx < 3; kx++) {
            int ww = w + kx - 1;
            if (ww < 0 || ww >= Wn) continue;
            const float* xr = X + ((size_t)((b * Hn + hh) * Wn + ww)) * 16;
            const float* wr = Wf + (ky * 3 + kx) * 16 * 2;
#pragma unroll
            for (int c = 0; c < 16; c++) {
                float xv = xr[c] * sc[c] + sh[c];
                f0 += xv * wr[c * 2 + 0];
                f1 += xv * wr[c * 2 + 1];
            }
        }
    }
    out[(size_t)pix * 2 + 0] = FLOW_SCALE * f0;
    out[(size_t)pix * 2 + 1] = FLOW_SCALE * f1;
}

// ---------------- launch ----------------
extern "C" void kernel_launch(void* const* d_in, const int* in_sizes, int n_in,
                              void* d_out, int out_size)
{
    const float* prv   = (const float*)d_in[0];
    const float* nxt   = (const float*)d_in[1];
    const float* dw0   = (const float*)d_in[2];
    const float* pw0   = (const float*)d_in[3];
    const float* b0    = (const float*)d_in[4];
    const float* dw1   = (const float*)d_in[5];
    const float* pw1   = (const float*)d_in[6];
    const float* b1    = (const float*)d_in[7];
    const float* dw2   = (const float*)d_in[8];
    const float* pw2   = (const float*)d_in[9];
    const float* b2    = (const float*)d_in[10];
    const float* dw3   = (const float*)d_in[11];
    const float* pw3   = (const float*)d_in[12];
    const float* b3    = (const float*)d_in[13];
    const float* bng   = (const float*)d_in[14];
    const float* bnb   = (const float*)d_in[15];
    const float* bnm   = (const float*)d_in[16];
    const float* bnv   = (const float*)d_in[17];
    const float* flw   = (const float*)d_in[18];
    float* out = (float*)d_out;

    float *A = nullptr, *Bb = nullptr, *W0 = nullptr;
    __nv_bfloat16 *W0h = nullptr, *W0l = nullptr, *W1h = nullptr, *W1l = nullptr;
    cudaGetSymbolAddress((void**)&A,   g_bufA);
    cudaGetSymbolAddress((void**)&Bb,  g_bufB);
    cudaGetSymbolAddress((void**)&W0,  g_dw0pad);
    cudaGetSymbolAddress((void**)&W0h, g_w0hi);
    cudaGetSymbolAddress((void**)&W0l, g_w0lo);
    cudaGetSymbolAddress((void**)&W1h, g_w1hi);
    cudaGetSymbolAddress((void**)&W1l, g_w1lo);

    prep_kernel<<<(224 * 128 + 255) / 256, 256>>>(dw0, pw0, pw1);

    // cost volume + concat -> A [NPIX, 216]
    {
        dim3 grid(Wn / 32, Hn / 8, Bn);
        cost_kernel<0, 5><<<grid, 128>>>(prv, nxt, A);
        cost_kernel<5, 4><<<grid, 128>>>(prv, nxt, A);
    }

    // layer 0: dw -> Bb(216); HMMA gemm -> A(128)
    dw4y_kernel<54, P0, P0><<<((NPIX / 4) * 54 + 255) / 256, 256>>>(A, W0, Bb);
    mma_gemm_mish<128, 14, P0><<<NPIX / 128, 256>>>(Bb, W0h, W0l, b0, A);
    // layer 1: dw -> Bb(128); HMMA gemm -> A(64)
    dw4y_kernel<32, 128, 128><<<((NPIX / 4) * 32 + 255) / 256, 256>>>(A, dw1, Bb);
    mma_gemm_mish<64, 8, 128><<<NPIX / 128, 256>>>(Bb, W1h, W1l, b1, A);
    // layer 2
    dw4y_kernel<16, 64, 64><<<((NPIX / 4) * 16 + 255) / 256, 256>>>(A, dw2, Bb);
    sgemm_mish<32, 2, 8><<<NPIX / 128, 256>>>(Bb, 64, pw2, b2, A);
    // layer 3
    dw4y_kernel<8, 32, 32><<<((NPIX / 4) * 8 + 255) / 256, 256>>>(A, dw3, Bb);
    sgemm_mish<16, 1, 4><<<NPIX / 128, 256>>>(Bb, 32, pw3, b3, A);

    final_kernel<<<(NPIX + 127) / 128, 128>>>(A, bng, bnb, bnm, bnv, flw, out);
}

// round 11
// speedup vs baseline: 1.3083x; 1.3083x over previous
#include <cuda_runtime.h>
#include <cuda_bf16.h>
#include <math.h>

// ---------------- problem constants ----------------
#define Bn 8
#define Hn 192
#define Wn 192
#define Cn 64
#define NPIX (Bn*Hn*Wn)          // 294912
#define CV 81
#define CIN0 209
#define P0 216                    // padded channel stride (27 * 8)
#define FLOW_SCALE 271.52900393598527f
#define BN_EPS 1e-3f

// ---------------- scratch ----------------
__device__ float g_bufA[(size_t)NPIX * P0];
__device__ float g_bufB[(size_t)NPIX * P0];
__device__ float g_dw0pad[9 * P0];
__device__ float g_pw0pad[P0 * 128];

__device__ __forceinline__ float mish(float x) {
    float sp = fmaxf(x, 0.f) + log1pf(expf(-fabsf(x)));
    return x * tanhf(sp);
}

// ---------------- packed f32x2 helpers ----------------
__device__ __forceinline__ unsigned long long pack2(float x, float y) {
    unsigned long long r;
    asm("mov.b64 %0, {%1, %2};" : "=l"(r) : "f"(x), "f"(y));
    return r;
}
__device__ __forceinline__ void unpack2(unsigned long long v, float& x, float& y) {
    asm("mov.b64 {%0, %1}, %2;" : "=f"(x), "=f"(y) : "l"(v));
}
__device__ __forceinline__ void ffma2(unsigned long long& c, unsigned long long a, unsigned long long b) {
    asm("fma.rn.f32x2 %0, %1, %2, %0;" : "+l"(c) : "l"(a), "l"(b));
}

// ---------------- kernel 0: pad dw0 + pw0 weights ----------------
__global__ void pad_w_kernel(const float* __restrict__ dw0, const float* __restrict__ pw0)
{
    int idx = blockIdx.x * blockDim.x + threadIdx.x;
    if (idx < 9 * P0) {
        int c = idx % P0;
        int k = idx / P0;
        g_dw0pad[idx] = (c < CIN0) ? dw0[k * CIN0 + c] : 0.f;
    }
    if (idx < P0 * 128) {
        int n = idx % 128;
        int k = idx / 128;
        g_pw0pad[idx] = (k < CIN0) ? pw0[k * 128 + n] : 0.f;
    }
}

// ---------------- kernel 1: cost volume (+ concat fold in DXB==0 pass) ----------------
template<int DXB, int NDX>
__global__ __launch_bounds__(128)
void cost_kernel(const float* __restrict__ prv, const float* __restrict__ nxt,
                 float* __restrict__ x0)
{
    __shared__ float sbuf[16 * 661];
    __shared__ float sout[NDX * 9 * 257];

    const int tid  = threadIdx.x;
    const int lane = tid & 31;
    const int wp   = tid >> 5;
    const int bx = blockIdx.x, by = blockIdx.y, b = blockIdx.z;

    const int x    = bx * 32 + lane;
    const int y0   = by * 8 + wp * 2;
    const size_t pix0 = (size_t)(b * Hn + y0) * Wn + x;
    const size_t pix1 = pix0 + Wn;

    float acc0[NDX * 9], acc1[NDX * 9];
#pragma unroll
    for (int t = 0; t < NDX * 9; t++) { acc0[t] = 0.f; acc1[t] = 0.f; }

#pragma unroll 1
    for (int chp = 0; chp < 4; chp++) {
        __syncthreads();
#pragma unroll 4
        for (int k = 0; k < 80; k++) {
            int i = tid + k * 128;
            int c = i & 15;
            int rest = i >> 4;
            int xs = rest % 40;
            int r  = rest / 40;
            int gy = by * 8 + r - 4;
            int gx = bx * 32 + xs - 4;
            float v = 0.f;
            if (gy >= 0 && gy < Hn && gx >= 0 && gx < Wn)
                v = nxt[((size_t)(b * Hn + gy) * Wn + gx) * Cn + chp * 16 + c];
            sbuf[c * 661 + r * 41 + xs] = v;
        }
        __syncthreads();

#pragma unroll 1
        for (int c4 = 0; c4 < 4; c4++) {
            float4 pa = *(const float4*)(prv + pix0 * Cn + chp * 16 + c4 * 4);
            float4 pb = *(const float4*)(prv + pix1 * Cn + chp * 16 + c4 * 4);
            float pav[4] = {pa.x, pa.y, pa.z, pa.w};
            float pbv[4] = {pb.x, pb.y, pb.z, pb.w};
#pragma unroll
            for (int cc = 0; cc < 4; cc++) {
                const float* splane = &sbuf[(c4 * 4 + cc) * 661];
#pragma unroll
                for (int rr = 0; rr < 10; rr++) {
                    const float* q = &splane[(wp * 2 + rr) * 41 + lane + DXB];
#pragma unroll
                    for (int d = 0; d < NDX; d++) {
                        float qv = q[d];
                        if (rr < 9)  acc0[rr * NDX + d]       = fmaf(pav[cc], qv, acc0[rr * NDX + d]);
                        if (rr >= 1) acc1[(rr - 1) * NDX + d] = fmaf(pbv[cc], qv, acc1[(rr - 1) * NDX + d]);
                    }
                }
            }
        }
    }

    __syncthreads();
    const int pl0 = wp * 64 + lane;
#pragma unroll
    for (int t = 0; t < NDX * 9; t++) {
        float v0 = acc0[t] * (1.f / 64.f); v0 = (v0 > 0.f) ? v0 : 0.1f * v0;
        float v1 = acc1[t] * (1.f / 64.f); v1 = (v1 > 0.f) ? v1 : 0.1f * v1;
        sout[t * 257 + pl0]      = v0;
        sout[t * 257 + pl0 + 32] = v1;
    }
    __syncthreads();

    const int TOT = 256 * NDX * 9;
    for (int i = tid; i < TOT; i += 128) {
        int px = i / (NDX * 9);
        int t  = i % (NDX * 9);
        int dy = t / NDX, d = t % NDX;
        int yl = px >> 5, xx = px & 31;
        size_t pix = (size_t)(b * Hn + by * 8 + yl) * Wn + bx * 32 + xx;
        x0[pix * P0 + dy * 9 + DXB + d] = sout[t * 257 + px];
    }

    if (DXB == 0) {
        for (int j = tid; j < 256 * 64; j += 128) {
            int px = j >> 6, c = j & 63;
            int yl = px >> 5, xx = px & 31;
            size_t pix = (size_t)(b * Hn + by * 8 + yl) * Wn + bx * 32 + xx;
            x0[pix * P0 + CV + c]      = prv[pix * Cn + c];
            x0[pix * P0 + CV + 64 + c] = nxt[pix * Cn + c];
            if (c >= 57) x0[pix * P0 + 152 + c] = 0.f;   // 209..215
        }
    }
}

// ---------------- kernel 2: depthwise 3x3, float4 channels, 4 y-outputs/thread ----------------
// __launch_bounds__(256, 4): cap regs at 64 -> 4 blocks/SM (occupancy fix; kernel is
// latency-bound at occ 34.5% with regs=70).
template<int QUADS, int STRIDE, int WSTRIDE>
__global__ __launch_bounds__(256, 4)
void dw4y_kernel(const float* __restrict__ X, const float* __restrict__ Wd,
                 float* __restrict__ Y)
{
    int idx = blockIdx.x * blockDim.x + threadIdx.x;
    if (idx >= (NPIX / 4) * QUADS) return;
    int q    = idx % QUADS;
    int rest = idx / QUADS;
    int w    = rest % Wn;
    int rest2 = rest / Wn;
    int hg   = rest2 % (Hn / 4);
    int b    = rest2 / (Hn / 4);
    const int h0 = hg * 4;

    float4 wv[9];
#pragma unroll
    for (int t = 0; t < 9; t++)
        wv[t] = *(const float4*)(Wd + t * WSTRIDE + q * 4);

    float4 acc[4];
#pragma unroll
    for (int m = 0; m < 4; m++) acc[m] = make_float4(0.f, 0.f, 0.f, 0.f);

    const bool wl = (w - 1 >= 0), wr = (w + 1 < Wn);

#pragma unroll
    for (int r = 0; r < 6; r++) {            // input rows h0-1 .. h0+4
        int hh = h0 + r - 1;
        if (hh < 0 || hh >= Hn) continue;
        const float* rowp = X + ((size_t)((b * Hn + hh) * Wn + w)) * STRIDE + q * 4;
#pragma unroll
        for (int kx = 0; kx < 3; kx++) {
            if (kx == 0 && !wl) continue;
            if (kx == 2 && !wr) continue;
            float4 xv = *(const float4*)(rowp + (kx - 1) * STRIDE);
#pragma unroll
            for (int m = 0; m < 4; m++) {
                int ky = r - m;               // input row = out_y + ky - 1
                if (ky < 0 || ky > 2) continue;
                float4 wq = wv[ky * 3 + kx];
                acc[m].x = fmaf(xv.x, wq.x, acc[m].x);
                acc[m].y = fmaf(xv.y, wq.y, acc[m].y);
                acc[m].z = fmaf(xv.z, wq.z, acc[m].z);
                acc[m].w = fmaf(xv.w, wq.w, acc[m].w);
            }
        }
    }

#pragma unroll
    for (int m = 0; m < 4; m++) {
        size_t pix = (size_t)((b * Hn + h0 + m) * Wn + w);
        *(float4*)(Y + pix * STRIDE + q * 4) = acc[m];
    }
}

// ---------------- kernel 3: SGEMM (f32x2) + bias + mish ----------------
template<int BN_, int TN_, int KTILES>
__global__ __launch_bounds__(256)
void sgemm_mish(const float* __restrict__ X, int ldX,
                const float* __restrict__ Wp,
                const float* __restrict__ bias,
                float* __restrict__ Y)
{
    __shared__ float As[2][8][128];
    __shared__ float Bs[2][8][BN_];

    const int tid = threadIdx.x;
    const int px0 = blockIdx.x * 128;

    const int arow = tid >> 1;
    const int acol = (tid & 1) * 4;
    const float* aptr = X + (size_t)(px0 + arow) * ldX + acol;

    constexpr int BLOADERS = BN_ * 2;
    const int brow = tid / (BN_ / 4);
    const int bcol = (tid % (BN_ / 4)) * 4;
    const float* bptr = Wp + (size_t)brow * BN_ + bcol;

    const int tcx = tid & 15;
    const int tcy = tid >> 4;

    unsigned long long accp[4][TN_];
#pragma unroll
    for (int j = 0; j < 4; j++)
#pragma unroll
        for (int n = 0; n < TN_; n++) accp[j][n] = 0ULL;

    float4 av = *(const float4*)aptr;
    float4 bv;
    if (tid < BLOADERS) bv = *(const float4*)bptr;

    As[0][acol + 0][arow] = av.x;
    As[0][acol + 1][arow] = av.y;
    As[0][acol + 2][arow] = av.z;
    As[0][acol + 3][arow] = av.w;
    if (tid < BLOADERS) *(float4*)&Bs[0][brow][bcol] = bv;
    __syncthreads();

#pragma unroll 1
    for (int kt = 0; kt < KTILES; kt++) {
        const int buf = kt & 1;
        if (kt + 1 < KTILES) {
            av = *(const float4*)(aptr + (kt + 1) * 8);
            if (tid < BLOADERS) bv = *(const float4*)(bptr + (size_t)(kt + 1) * 8 * BN_);
        }
#pragma unroll
        for (int kk = 0; kk < 8; kk++) {
            float4 a0 = *(const float4*)&As[buf][kk][tcy * 4];
            float4 a1 = *(const float4*)&As[buf][kk][tcy * 4 + 64];
            unsigned long long ap[4];
            ap[0] = pack2(a0.x, a0.y);
            ap[1] = pack2(a0.z, a0.w);
            ap[2] = pack2(a1.x, a1.y);
            ap[3] = pack2(a1.z, a1.w);

            float br[TN_];
            if constexpr (TN_ == 8) {
                float4 b0 = *(const float4*)&Bs[buf][kk][tcx * 4];
                float4 b1 = *(const float4*)&Bs[buf][kk][tcx * 4 + 64];
                br[0] = b0.x; br[1] = b0.y; br[2] = b0.z; br[3] = b0.w;
                br[4] = b1.x; br[5] = b1.y; br[6] = b1.z; br[7] = b1.w;
            } else if constexpr (TN_ == 4) {
                float4 b0 = *(const float4*)&Bs[buf][kk][tcx * 4];
                br[0] = b0.x; br[1] = b0.y; br[2] = b0.z; br[3] = b0.w;
            } else if constexpr (TN_ == 2) {
                float2 b0 = *(const float2*)&Bs[buf][kk][tcx * 2];
                br[0] = b0.x; br[1] = b0.y;
            } else {
                br[0] = Bs[buf][kk][tcx];
            }
            unsigned long long bd[TN_];
#pragma unroll
            for (int n = 0; n < TN_; n++) bd[n] = pack2(br[n], br[n]);
#pragma unroll
            for (int j = 0; j < 4; j++)
#pragma unroll
                for (int n = 0; n < TN_; n++)
                    ffma2(accp[j][n], ap[j], bd[n]);
        }
        if (kt + 1 < KTILES) {
            const int nb = buf ^ 1;
            As[nb][acol + 0][arow] = av.x;
            As[nb][acol + 1][arow] = av.y;
            As[nb][acol + 2][arow] = av.z;
            As[nb][acol + 3][arow] = av.w;
            if (tid < BLOADERS) *(float4*)&Bs[nb][brow][bcol] = bv;
        }
        __syncthreads();
    }

    float acc[8][TN_];
#pragma unroll
    for (int j = 0; j < 4; j++)
#pragma unroll
        for (int n = 0; n < TN_; n++)
            unpack2(accp[j][n], acc[2 * j][n], acc[2 * j + 1][n]);

    float bb[TN_];
    if constexpr (TN_ == 8) {
        float4 t0 = *(const float4*)&bias[tcx * 4];
        float4 t1 = *(const float4*)&bias[tcx * 4 + 64];
        bb[0]=t0.x; bb[1]=t0.y; bb[2]=t0.z; bb[3]=t0.w;
        bb[4]=t1.x; bb[5]=t1.y; bb[6]=t1.z; bb[7]=t1.w;
    } else if constexpr (TN_ == 4) {
        float4 t0 = *(const float4*)&bias[tcx * 4];
        bb[0]=t0.x; bb[1]=t0.y; bb[2]=t0.z; bb[3]=t0.w;
    } else if constexpr (TN_ == 2) {
        float2 t0 = *(const float2*)&bias[tcx * 2];
        bb[0]=t0.x; bb[1]=t0.y;
    } else {
        bb[0] = bias[tcx];
    }

#pragma unroll
    for (int g = 0; g < 2; g++) {
#pragma unroll
        for (int m = 0; m < 4; m++) {
            int px = px0 + tcy * 4 + m + g * 64;
            float* yr = Y + (size_t)px * BN_;
            float ov[TN_];
#pragma unroll
            for (int n = 0; n < TN_; n++) ov[n] = mish(acc[g * 4 + m][n] + bb[n]);
            if constexpr (TN_ == 8) {
                *(float4*)&yr[tcx * 4]      = make_float4(ov[0], ov[1], ov[2], ov[3]);
                *(float4*)&yr[tcx * 4 + 64] = make_float4(ov[4], ov[5], ov[6], ov[7]);
            } else if constexpr (TN_ == 4) {
                *(float4*)&yr[tcx * 4] = make_float4(ov[0], ov[1], ov[2], ov[3]);
            } else if constexpr (TN_ == 2) {
                *(float2*)&yr[tcx * 2] = make_float2(ov[0], ov[1]);
            } else {
                yr[tcx] = ov[0];
            }
        }
    }
}

// ---------------- kernel 4: BN + 3x3 flow conv + scale ----------------
__global__ void final_kernel(const float* __restrict__ X,
                             const float* __restrict__ gamma, const float* __restrict__ beta,
                             const float* __restrict__ mean,  const float* __restrict__ var,
                             const float* __restrict__ Wf, float* __restrict__ out)
{
    int pix = blockIdx.x * blockDim.x + threadIdx.x;
    if (pix >= NPIX) return;
    int w = pix % Wn;
    int h = (pix / Wn) % Hn;
    int b = pix / (Wn * Hn);

    float sc[16], sh[16];
#pragma unroll
    for (int c = 0; c < 16; c++) {
        float s = gamma[c] * rsqrtf(var[c] + BN_EPS);
        sc[c] = s;
        sh[c] = beta[c] - mean[c] * s;
    }

    float f0 = 0.f, f1 = 0.f;
#pragma unroll
    for (int ky = 0; ky < 3; ky++) {
        int hh = h + ky - 1;
        if (hh < 0 || hh >= Hn) continue;
#pragma unroll
        for (int kx = 0; kx < 3; kx++) {
            int ww = w + kx - 1;
            if (ww < 0 || ww >= Wn) continue;
            const float* xr = X + ((size_t)((b * Hn + hh) * Wn + ww)) * 16;
            const float* wr = Wf + (ky * 3 + kx) * 16 * 2;
#pragma unroll
            for (int c = 0; c < 16; c++) {
                float xv = xr[c] * sc[c] + sh[c];
                f0 += xv * wr[c * 2 + 0];
                f1 += xv * wr[c * 2 + 1];
            }
        }
    }
    out[(size_t)pix * 2 + 0] = FLOW_SCALE * f0;
    out[(size_t)pix * 2 + 1] = FLOW_SCALE * f1;
}

// ---------------- launch ----------------
extern "C" void kernel_launch(void* const* d_in, const int* in_sizes, int n_in,
                              void* d_out, int out_size)
{
    const float* prv   = (const float*)d_in[0];
    const float* nxt   = (const float*)d_in[1];
    const float* dw0   = (const float*)d_in[2];
    const float* pw0   = (const float*)d_in[3];
    const float* b0    = (const float*)d_in[4];
    const float* dw1   = (const float*)d_in[5];
    const float* pw1   = (const float*)d_in[6];
    const float* b1    = (const float*)d_in[7];
    const float* dw2   = (const float*)d_in[8];
    const float* pw2   = (const float*)d_in[9];
    const float* b2    = (const float*)d_in[10];
    const float* dw3   = (const float*)d_in[11];
    const float* pw3   = (const float*)d_in[12];
    const float* b3    = (const float*)d_in[13];
    const float* bng   = (const float*)d_in[14];
    const float* bnb   = (const float*)d_in[15];
    const float* bnm   = (const float*)d_in[16];
    const float* bnv   = (const float*)d_in[17];
    const float* flw   = (const float*)d_in[18];
    float* out = (float*)d_out;

    float *A = nullptr, *Bb = nullptr, *W0 = nullptr, *PW0 = nullptr;
    cudaGetSymbolAddress((void**)&A,   g_bufA);
    cudaGetSymbolAddress((void**)&Bb,  g_bufB);
    cudaGetSymbolAddress((void**)&W0,  g_dw0pad);
    cudaGetSymbolAddress((void**)&PW0, g_pw0pad);

    pad_w_kernel<<<(P0 * 128 + 255) / 256, 256>>>(dw0, pw0);

    // cost volume + concat -> A [NPIX, 216]
    {
        dim3 grid(Wn / 32, Hn / 8, Bn);
        cost_kernel<0, 5><<<grid, 128>>>(prv, nxt, A);
        cost_kernel<5, 4><<<grid, 128>>>(prv, nxt, A);
    }

    // layer 0
    dw4y_kernel<54, P0, P0><<<((NPIX / 4) * 54 + 255) / 256, 256>>>(A, W0, Bb);
    sgemm_mish<128, 8, P0 / 8><<<NPIX / 128, 256>>>(Bb, P0, PW0, b0, A);
    // layer 1
    dw4y_kernel<32, 128, 128><<<((NPIX / 4) * 32 + 255) / 256, 256>>>(A, dw1, Bb);
    sgemm_mish<64, 4, 16><<<NPIX / 128, 256>>>(Bb, 128, pw1, b1, A);
    // layer 2
    dw4y_kernel<16, 64, 64><<<((NPIX / 4) * 16 + 255) / 256, 256>>>(A, dw2, Bb);
    sgemm_mish<32, 2, 8><<<NPIX / 128, 256>>>(Bb, 64, pw2, b2, A);
    // layer 3
    dw4y_kernel<8, 32, 32><<<((NPIX / 4) * 8 + 255) / 256, 256>>>(A, dw3, Bb);
    sgemm_mish<16, 1, 4><<<NPIX / 128, 256>>>(Bb, 32, pw3, b3, A);

    final_kernel<<<(NPIX + 127) / 128, 128>>>(A, bng, bnb, bnm, bnv, flw, out);
}

// round 12
// speedup vs baseline: 1.4851x; 1.1351x over previous
#include <cuda_runtime.h>
#include <cuda_fp16.h>
#include <math.h>

// ---------------- problem constants ----------------
#define Bn 8
#define Hn 192
#define Wn 192
#define Cn 64
#define NPIX (Bn*Hn*Wn)          // 294912
#define CV 81
#define CIN0 209
#define P0 216                    // padded channel stride (27 * 8)
#define FLOW_SCALE 271.52900393598527f
#define BN_EPS 1e-3f

// ---------------- scratch (activations in fp16) ----------------
__device__ __half g_bufA[(size_t)NPIX * P0];
__device__ __half g_bufB[(size_t)NPIX * P0];
__device__ float g_dw0pad[9 * P0];
__device__ float g_pw0pad[P0 * 128];

__device__ __forceinline__ float mish(float x) {
    float sp = fmaxf(x, 0.f) + log1pf(expf(-fabsf(x)));
    return x * tanhf(sp);
}

// ---------------- packed f32x2 helpers ----------------
__device__ __forceinline__ unsigned long long pack2(float x, float y) {
    unsigned long long r;
    asm("mov.b64 %0, {%1, %2};" : "=l"(r) : "f"(x), "f"(y));
    return r;
}
__device__ __forceinline__ void unpack2(unsigned long long v, float& x, float& y) {
    asm("mov.b64 {%0, %1}, %2;" : "=f"(x), "=f"(y) : "l"(v));
}
__device__ __forceinline__ void ffma2(unsigned long long& c, unsigned long long a, unsigned long long b) {
    asm("fma.rn.f32x2 %0, %1, %2, %0;" : "+l"(c) : "l"(a), "l"(b));
}

// half4 <-> float helpers
__device__ __forceinline__ void h4_to_f(const uint2 raw, float* f) {
    __half2 h0 = *(const __half2*)&raw.x;
    __half2 h1 = *(const __half2*)&raw.y;
    float2 a = __half22float2(h0), b = __half22float2(h1);
    f[0] = a.x; f[1] = a.y; f[2] = b.x; f[3] = b.y;
}
__device__ __forceinline__ uint2 f_to_h4(float a, float b, float c, float d) {
    __half2 h0 = __floats2half2_rn(a, b);
    __half2 h1 = __floats2half2_rn(c, d);
    uint2 r;
    r.x = *(const unsigned*)&h0;
    r.y = *(const unsigned*)&h1;
    return r;
}

// ---------------- kernel 0: pad dw0 + pw0 weights ----------------
__global__ void pad_w_kernel(const float* __restrict__ dw0, const float* __restrict__ pw0)
{
    int idx = blockIdx.x * blockDim.x + threadIdx.x;
    if (idx < 9 * P0) {
        int c = idx % P0;
        int k = idx / P0;
        g_dw0pad[idx] = (c < CIN0) ? dw0[k * CIN0 + c] : 0.f;
    }
    if (idx < P0 * 128) {
        int n = idx % 128;
        int k = idx / 128;
        g_pw0pad[idx] = (k < CIN0) ? pw0[k * 128 + n] : 0.f;
    }
}

// ---------------- kernel 1: cost volume (+ concat fold in DXB==0 pass) ----------------
template<int DXB, int NDX>
__global__ __launch_bounds__(128)
void cost_kernel(const float* __restrict__ prv, const float* __restrict__ nxt,
                 __half* __restrict__ x0)
{
    __shared__ float sbuf[16 * 661];
    __shared__ float sout[NDX * 9 * 257];

    const int tid  = threadIdx.x;
    const int lane = tid & 31;
    const int wp   = tid >> 5;
    const int bx = blockIdx.x, by = blockIdx.y, b = blockIdx.z;

    const int x    = bx * 32 + lane;
    const int y0   = by * 8 + wp * 2;
    const size_t pix0 = (size_t)(b * Hn + y0) * Wn + x;
    const size_t pix1 = pix0 + Wn;

    float acc0[NDX * 9], acc1[NDX * 9];
#pragma unroll
    for (int t = 0; t < NDX * 9; t++) { acc0[t] = 0.f; acc1[t] = 0.f; }

#pragma unroll 1
    for (int chp = 0; chp < 4; chp++) {
        __syncthreads();
#pragma unroll 4
        for (int k = 0; k < 80; k++) {
            int i = tid + k * 128;
            int c = i & 15;
            int rest = i >> 4;
            int xs = rest % 40;
            int r  = rest / 40;
            int gy = by * 8 + r - 4;
            int gx = bx * 32 + xs - 4;
            float v = 0.f;
            if (gy >= 0 && gy < Hn && gx >= 0 && gx < Wn)
                v = nxt[((size_t)(b * Hn + gy) * Wn + gx) * Cn + chp * 16 + c];
            sbuf[c * 661 + r * 41 + xs] = v;
        }
        __syncthreads();

#pragma unroll 1
        for (int c4 = 0; c4 < 4; c4++) {
            float4 pa = *(const float4*)(prv + pix0 * Cn + chp * 16 + c4 * 4);
            float4 pb = *(const float4*)(prv + pix1 * Cn + chp * 16 + c4 * 4);
            float pav[4] = {pa.x, pa.y, pa.z, pa.w};
            float pbv[4] = {pb.x, pb.y, pb.z, pb.w};
#pragma unroll
            for (int cc = 0; cc < 4; cc++) {
                const float* splane = &sbuf[(c4 * 4 + cc) * 661];
#pragma unroll
                for (int rr = 0; rr < 10; rr++) {
                    const float* q = &splane[(wp * 2 + rr) * 41 + lane + DXB];
#pragma unroll
                    for (int d = 0; d < NDX; d++) {
                        float qv = q[d];
                        if (rr < 9)  acc0[rr * NDX + d]       = fmaf(pav[cc], qv, acc0[rr * NDX + d]);
                        if (rr >= 1) acc1[(rr - 1) * NDX + d] = fmaf(pbv[cc], qv, acc1[(rr - 1) * NDX + d]);
                    }
                }
            }
        }
    }

    __syncthreads();
    const int pl0 = wp * 64 + lane;
#pragma unroll
    for (int t = 0; t < NDX * 9; t++) {
        float v0 = acc0[t] * (1.f / 64.f); v0 = (v0 > 0.f) ? v0 : 0.1f * v0;
        float v1 = acc1[t] * (1.f / 64.f); v1 = (v1 > 0.f) ? v1 : 0.1f * v1;
        sout[t * 257 + pl0]      = v0;
        sout[t * 257 + pl0 + 32] = v1;
    }
    __syncthreads();

    const int TOT = 256 * NDX * 9;
    for (int i = tid; i < TOT; i += 128) {
        int px = i / (NDX * 9);
        int t  = i % (NDX * 9);
        int dy = t / NDX, d = t % NDX;
        int yl = px >> 5, xx = px & 31;
        size_t pix = (size_t)(b * Hn + by * 8 + yl) * Wn + bx * 32 + xx;
        x0[pix * P0 + dy * 9 + DXB + d] = __float2half_rn(sout[t * 257 + px]);
    }

    if (DXB == 0) {
        for (int j = tid; j < 256 * 64; j += 128) {
            int px = j >> 6, c = j & 63;
            int yl = px >> 5, xx = px & 31;
            size_t pix = (size_t)(b * Hn + by * 8 + yl) * Wn + bx * 32 + xx;
            x0[pix * P0 + CV + c]      = __float2half_rn(prv[pix * Cn + c]);
            x0[pix * P0 + CV + 64 + c] = __float2half_rn(nxt[pix * Cn + c]);
            if (c >= 57) x0[pix * P0 + 152 + c] = __float2half_rn(0.f);   // 209..215
        }
    }
}

// ---------------- kernel 2: depthwise 3x3, half4 channels, 4 y-outputs/thread ----------------
template<int QUADS, int STRIDE, int WSTRIDE>
__global__ __launch_bounds__(256, 4)
void dw4y_kernel(const __half* __restrict__ X, const float* __restrict__ Wd,
                 __half* __restrict__ Y)
{
    int idx = blockIdx.x * blockDim.x + threadIdx.x;
    if (idx >= (NPIX / 4) * QUADS) return;
    int q    = idx % QUADS;
    int rest = idx / QUADS;
    int w    = rest % Wn;
    int rest2 = rest / Wn;
    int hg   = rest2 % (Hn / 4);
    int b    = rest2 / (Hn / 4);
    const int h0 = hg * 4;

    float4 wv[9];
#pragma unroll
    for (int t = 0; t < 9; t++)
        wv[t] = *(const float4*)(Wd + t * WSTRIDE + q * 4);

    float4 acc[4];
#pragma unroll
    for (int m = 0; m < 4; m++) acc[m] = make_float4(0.f, 0.f, 0.f, 0.f);

    const bool wl = (w - 1 >= 0), wr = (w + 1 < Wn);

#pragma unroll
    for (int r = 0; r < 6; r++) {            // input rows h0-1 .. h0+4
        int hh = h0 + r - 1;
        if (hh < 0 || hh >= Hn) continue;
        const __half* rowp = X + ((size_t)((b * Hn + hh) * Wn + w)) * STRIDE + q * 4;
#pragma unroll
        for (int kx = 0; kx < 3; kx++) {
            if (kx == 0 && !wl) continue;
            if (kx == 2 && !wr) continue;
            uint2 raw = *(const uint2*)(rowp + (kx - 1) * STRIDE);
            float xv[4];
            h4_to_f(raw, xv);
#pragma unroll
            for (int m = 0; m < 4; m++) {
                int ky = r - m;               // input row = out_y + ky - 1
                if (ky < 0 || ky > 2) continue;
                float4 wq = wv[ky * 3 + kx];
                acc[m].x = fmaf(xv[0], wq.x, acc[m].x);
                acc[m].y = fmaf(xv[1], wq.y, acc[m].y);
                acc[m].z = fmaf(xv[2], wq.z, acc[m].z);
                acc[m].w = fmaf(xv[3], wq.w, acc[m].w);
            }
        }
    }

#pragma unroll
    for (int m = 0; m < 4; m++) {
        size_t pix = (size_t)((b * Hn + h0 + m) * Wn + w);
        *(uint2*)(Y + pix * STRIDE + q * 4) = f_to_h4(acc[m].x, acc[m].y, acc[m].z, acc[m].w);
    }
}

// ---------------- kernel 3: SGEMM (f32x2) + bias + mish, fp16 I/O ----------------
// BM=128, BK=8, 256 threads, microtile 8 x TN_ via 4 m-pairs of f32x2.
template<int BN_, int TN_, int KTILES>
__global__ __launch_bounds__(256)
void sgemm_mish(const __half* __restrict__ X, int ldX,
                const float* __restrict__ Wp,
                const float* __restrict__ bias,
                __half* __restrict__ Y)
{
    __shared__ float As[2][8][128];
    __shared__ float Bs[2][8][BN_];

    const int tid = threadIdx.x;
    const int px0 = blockIdx.x * 128;

    const int arow = tid >> 1;
    const int acol = (tid & 1) * 4;
    const __half* aptr = X + (size_t)(px0 + arow) * ldX + acol;

    constexpr int BLOADERS = BN_ * 2;
    const int brow = tid / (BN_ / 4);
    const int bcol = (tid % (BN_ / 4)) * 4;
    const float* bptr = Wp + (size_t)brow * BN_ + bcol;

    const int tcx = tid & 15;
    const int tcy = tid >> 4;

    unsigned long long accp[4][TN_];
#pragma unroll
    for (int j = 0; j < 4; j++)
#pragma unroll
        for (int n = 0; n < TN_; n++) accp[j][n] = 0ULL;

    uint2 araw = *(const uint2*)aptr;
    float4 bv;
    if (tid < BLOADERS) bv = *(const float4*)bptr;

    {
        float af[4];
        h4_to_f(araw, af);
        As[0][acol + 0][arow] = af[0];
        As[0][acol + 1][arow] = af[1];
        As[0][acol + 2][arow] = af[2];
        As[0][acol + 3][arow] = af[3];
    }
    if (tid < BLOADERS) *(float4*)&Bs[0][brow][bcol] = bv;
    __syncthreads();

#pragma unroll 1
    for (int kt = 0; kt < KTILES; kt++) {
        const int buf = kt & 1;
        if (kt + 1 < KTILES) {
            araw = *(const uint2*)(aptr + (kt + 1) * 8);
            if (tid < BLOADERS) bv = *(const float4*)(bptr + (size_t)(kt + 1) * 8 * BN_);
        }
#pragma unroll
        for (int kk = 0; kk < 8; kk++) {
            float4 a0 = *(const float4*)&As[buf][kk][tcy * 4];
            float4 a1 = *(const float4*)&As[buf][kk][tcy * 4 + 64];
            unsigned long long ap[4];
            ap[0] = pack2(a0.x, a0.y);
            ap[1] = pack2(a0.z, a0.w);
            ap[2] = pack2(a1.x, a1.y);
            ap[3] = pack2(a1.z, a1.w);

            float br[TN_];
            if constexpr (TN_ == 8) {
                float4 b0 = *(const float4*)&Bs[buf][kk][tcx * 4];
                float4 b1 = *(const float4*)&Bs[buf][kk][tcx * 4 + 64];
                br[0] = b0.x; br[1] = b0.y; br[2] = b0.z; br[3] = b0.w;
                br[4] = b1.x; br[5] = b1.y; br[6] = b1.z; br[7] = b1.w;
            } else if constexpr (TN_ == 4) {
                float4 b0 = *(const float4*)&Bs[buf][kk][tcx * 4];
                br[0] = b0.x; br[1] = b0.y; br[2] = b0.z; br[3] = b0.w;
            } else if constexpr (TN_ == 2) {
                float2 b0 = *(const float2*)&Bs[buf][kk][tcx * 2];
                br[0] = b0.x; br[1] = b0.y;
            } else {
                br[0] = Bs[buf][kk][tcx];
            }
            unsigned long long bd[TN_];
#pragma unroll
            for (int n = 0; n < TN_; n++) bd[n] = pack2(br[n], br[n]);
#pragma unroll
            for (int j = 0; j < 4; j++)
#pragma unroll
                for (int n = 0; n < TN_; n++)
                    ffma2(accp[j][n], ap[j], bd[n]);
        }
        if (kt + 1 < KTILES) {
            const int nb = buf ^ 1;
            float af[4];
            h4_to_f(araw, af);
            As[nb][acol + 0][arow] = af[0];
            As[nb][acol + 1][arow] = af[1];
            As[nb][acol + 2][arow] = af[2];
            As[nb][acol + 3][arow] = af[3];
            if (tid < BLOADERS) *(float4*)&Bs[nb][brow][bcol] = bv;
        }
        __syncthreads();
    }

    float acc[8][TN_];
#pragma unroll
    for (int j = 0; j < 4; j++)
#pragma unroll
        for (int n = 0; n < TN_; n++)
            unpack2(accp[j][n], acc[2 * j][n], acc[2 * j + 1][n]);

    float bb[TN_];
    if constexpr (TN_ == 8) {
        float4 t0 = *(const float4*)&bias[tcx * 4];
        float4 t1 = *(const float4*)&bias[tcx * 4 + 64];
        bb[0]=t0.x; bb[1]=t0.y; bb[2]=t0.z; bb[3]=t0.w;
        bb[4]=t1.x; bb[5]=t1.y; bb[6]=t1.z; bb[7]=t1.w;
    } else if constexpr (TN_ == 4) {
        float4 t0 = *(const float4*)&bias[tcx * 4];
        bb[0]=t0.x; bb[1]=t0.y; bb[2]=t0.z; bb[3]=t0.w;
    } else if constexpr (TN_ == 2) {
        float2 t0 = *(const float2*)&bias[tcx * 2];
        bb[0]=t0.x; bb[1]=t0.y;
    } else {
        bb[0] = bias[tcx];
    }

#pragma unroll
    for (int g = 0; g < 2; g++) {
#pragma unroll
        for (int m = 0; m < 4; m++) {
            int px = px0 + tcy * 4 + m + g * 64;
            __half* yr = Y + (size_t)px * BN_;
            float ov[TN_];
#pragma unroll
            for (int n = 0; n < TN_; n++) ov[n] = mish(acc[g * 4 + m][n] + bb[n]);
            if constexpr (TN_ == 8) {
                *(uint2*)&yr[tcx * 4]      = f_to_h4(ov[0], ov[1], ov[2], ov[3]);
                *(uint2*)&yr[tcx * 4 + 64] = f_to_h4(ov[4], ov[5], ov[6], ov[7]);
            } else if constexpr (TN_ == 4) {
                *(uint2*)&yr[tcx * 4] = f_to_h4(ov[0], ov[1], ov[2], ov[3]);
            } else if constexpr (TN_ == 2) {
                __half2 h = __floats2half2_rn(ov[0], ov[1]);
                *(__half2*)&yr[tcx * 2] = h;
            } else {
                yr[tcx] = __float2half_rn(ov[0]);
            }
        }
    }
}

// ---------------- kernel 4: BN + 3x3 flow conv + scale ----------------
__global__ void final_kernel(const __half* __restrict__ X,
                             const float* __restrict__ gamma, const float* __restrict__ beta,
                             const float* __restrict__ mean,  const float* __restrict__ var,
                             const float* __restrict__ Wf, float* __restrict__ out)
{
    int pix = blockIdx.x * blockDim.x + threadIdx.x;
    if (pix >= NPIX) return;
    int w = pix % Wn;
    int h = (pix / Wn) % Hn;
    int b = pix / (Wn * Hn);

    float sc[16], sh[16];
#pragma unroll
    for (int c = 0; c < 16; c++) {
        float s = gamma[c] * rsqrtf(var[c] + BN_EPS);
        sc[c] = s;
        sh[c] = beta[c] - mean[c] * s;
    }

    float f0 = 0.f, f1 = 0.f;
#pragma unroll
    for (int ky = 0; ky < 3; ky++) {
        int hh = h + ky - 1;
        if (hh < 0 || hh >= Hn) continue;
#pragma unroll
        for (int kx = 0; kx < 3; kx++) {
            int ww = w + kx - 1;
            if (ww < 0 || ww >= Wn) continue;
            const __half* xr = X + ((size_t)((b * Hn + hh) * Wn + ww)) * 16;
            const float* wr = Wf + (ky * 3 + kx) * 16 * 2;
            uint2 r0 = *(const uint2*)(xr);
            uint2 r1 = *(const uint2*)(xr + 4);
            uint2 r2 = *(const uint2*)(xr + 8);
            uint2 r3 = *(const uint2*)(xr + 12);
            float xf[16];
            h4_to_f(r0, xf);
            h4_to_f(r1, xf + 4);
            h4_to_f(r2, xf + 8);
            h4_to_f(r3, xf + 12);
#pragma unroll
            for (int c = 0; c < 16; c++) {
                float xv = xf[c] * sc[c] + sh[c];
                f0 += xv * wr[c * 2 + 0];
                f1 += xv * wr[c * 2 + 1];
            }
        }
    }
    out[(size_t)pix * 2 + 0] = FLOW_SCALE * f0;
    out[(size_t)pix * 2 + 1] = FLOW_SCALE * f1;
}

// ---------------- launch ----------------
extern "C" void kernel_launch(void* const* d_in, const int* in_sizes, int n_in,
                              void* d_out, int out_size)
{
    const float* prv   = (const float*)d_in[0];
    const float* nxt   = (const float*)d_in[1];
    const float* dw0   = (const float*)d_in[2];
    const float* pw0   = (const float*)d_in[3];
    const float* b0    = (const float*)d_in[4];
    const float* dw1   = (const float*)d_in[5];
    const float* pw1   = (const float*)d_in[6];
    const float* b1    = (const float*)d_in[7];
    const float* dw2   = (const float*)d_in[8];
    const float* pw2   = (const float*)d_in[9];
    const float* b2    = (const float*)d_in[10];
    const float* dw3   = (const float*)d_in[11];
    const float* pw3   = (const float*)d_in[12];
    const float* b3    = (const float*)d_in[13];
    const float* bng   = (const float*)d_in[14];
    const float* bnb   = (const float*)d_in[15];
    const float* bnm   = (const float*)d_in[16];
    const float* bnv   = (const float*)d_in[17];
    const float* flw   = (const float*)d_in[18];
    float* out = (float*)d_out;

    __half *A = nullptr, *Bb = nullptr;
    float *W0 = nullptr, *PW0 = nullptr;
    cudaGetSymbolAddress((void**)&A,   g_bufA);
    cudaGetSymbolAddress((void**)&Bb,  g_bufB);
    cudaGetSymbolAddress((void**)&W0,  g_dw0pad);
    cudaGetSymbolAddress((void**)&PW0, g_pw0pad);

    pad_w_kernel<<<(P0 * 128 + 255) / 256, 256>>>(dw0, pw0);

    // cost volume + concat -> A [NPIX, 216] fp16
    {
        dim3 grid(Wn / 32, Hn / 8, Bn);
        cost_kernel<0, 5><<<grid, 128>>>(prv, nxt, A);
        cost_kernel<5, 4><<<grid, 128>>>(prv, nxt, A);
    }

    // layer 0
    dw4y_kernel<54, P0, P0><<<((NPIX / 4) * 54 + 255) / 256, 256>>>(A, W0, Bb);
    sgemm_mish<128, 8, P0 / 8><<<NPIX / 128, 256>>>(Bb, P0, PW0, b0, A);
    // layer 1
    dw4y_kernel<32, 128, 128><<<((NPIX / 4) * 32 + 255) / 256, 256>>>(A, dw1, Bb);
    sgemm_mish<64, 4, 16><<<NPIX / 128, 256>>>(Bb, 128, pw1, b1, A);
    // layer 2
    dw4y_kernel<16, 64, 64><<<((NPIX / 4) * 16 + 255) / 256, 256>>>(A, dw2, Bb);
    sgemm_mish<32, 2, 8><<<NPIX / 128, 256>>>(Bb, 64, pw2, b2, A);
    // layer 3
    dw4y_kernel<8, 32, 32><<<((NPIX / 4) * 8 + 255) / 256, 256>>>(A, dw3, Bb);
    sgemm_mish<16, 1, 4><<<NPIX / 128, 256>>>(Bb, 32, pw3, b3, A);

    final_kernel<<<(NPIX + 127) / 128, 128>>>(A, bng, bnb, bnm, bnv, flw, out);
}

// round 14
// speedup vs baseline: 1.5744x; 1.0601x over previous
#include <cuda_runtime.h>
#include <cuda_fp16.h>
#include <math.h>

// ---------------- problem constants ----------------
#define Bn 8
#define Hn 192
#define Wn 192
#define Cn 64
#define NPIX (Bn*Hn*Wn)          // 294912
#define CV 81
#define CIN0 209
#define P0 216                    // padded channel stride (27 * 8)
#define FLOW_SCALE 271.52900393598527f
#define BN_EPS 1e-3f

// ---------------- scratch (activations in fp16) ----------------
__device__ __half g_bufA[(size_t)NPIX * P0];
__device__ __half g_bufB[(size_t)NPIX * P0];
__device__ float g_dw0pad[9 * P0];
__device__ float g_pw0pad[P0 * 128];

// mish via identity: tanh(softplus(x)) = (s^2+2s)/(s^2+2s+2), s=e^x.
// For x>15, tanh(softplus(x)) = 1 - O(1e-13) -> return x (also guards s^2 overflow).
__device__ __forceinline__ float mish(float x) {
    float s = __expf(x);
    float t = s * (s + 2.f);
    float r = x * __fdividef(t, t + 2.f);
    return (x > 15.f) ? x : r;
}

// ---------------- packed f32x2 helpers ----------------
__device__ __forceinline__ unsigned long long pack2(float x, float y) {
    unsigned long long r;
    asm("mov.b64 %0, {%1, %2};" : "=l"(r) : "f"(x), "f"(y));
    return r;
}
__device__ __forceinline__ void unpack2(unsigned long long v, float& x, float& y) {
    asm("mov.b64 {%0, %1}, %2;" : "=f"(x), "=f"(y) : "l"(v));
}
__device__ __forceinline__ void ffma2(unsigned long long& c, unsigned long long a, unsigned long long b) {
    asm("fma.rn.f32x2 %0, %1, %2, %0;" : "+l"(c) : "l"(a), "l"(b));
}

// half4 <-> float helpers
__device__ __forceinline__ void h4_to_f(const uint2 raw, float* f) {
    __half2 h0 = *(const __half2*)&raw.x;
    __half2 h1 = *(const __half2*)&raw.y;
    float2 a = __half22float2(h0), b = __half22float2(h1);
    f[0] = a.x; f[1] = a.y; f[2] = b.x; f[3] = b.y;
}
__device__ __forceinline__ uint2 f_to_h4(float a, float b, float c, float d) {
    __half2 h0 = __floats2half2_rn(a, b);
    __half2 h1 = __floats2half2_rn(c, d);
    uint2 r;
    r.x = *(const unsigned*)&h0;
    r.y = *(const unsigned*)&h1;
    return r;
}

// ---------------- kernel 0: pad dw0 + pw0 weights ----------------
__global__ void pad_w_kernel(const float* __restrict__ dw0, const float* __restrict__ pw0)
{
    int idx = blockIdx.x * blockDim.x + threadIdx.x;
    if (idx < 9 * P0) {
        int c = idx % P0;
        int k = idx / P0;
        g_dw0pad[idx] = (c < CIN0) ? dw0[k * CIN0 + c] : 0.f;
    }
    if (idx < P0 * 128) {
        int n = idx % 128;
        int k = idx / 128;
        g_pw0pad[idx] = (k < CIN0) ? pw0[k * 128 + n] : 0.f;
    }
}

// ---------------- kernel 1: cost volume (+ concat fold in DXB==0 pass) ----------------
template<int DXB, int NDX>
__global__ __launch_bounds__(128)
void cost_kernel(const float* __restrict__ prv, const float* __restrict__ nxt,
                 __half* __restrict__ x0)
{
    __shared__ float sbuf[16 * 661];
    __shared__ float sout[NDX * 9 * 257];

    const int tid  = threadIdx.x;
    const int lane = tid & 31;
    const int wp   = tid >> 5;
    const int bx = blockIdx.x, by = blockIdx.y, b = blockIdx.z;

    const int x    = bx * 32 + lane;
    const int y0   = by * 8 + wp * 2;
    const size_t pix0 = (size_t)(b * Hn + y0) * Wn + x;
    const size_t pix1 = pix0 + Wn;

    float acc0[NDX * 9], acc1[NDX * 9];
#pragma unroll
    for (int t = 0; t < NDX * 9; t++) { acc0[t] = 0.f; acc1[t] = 0.f; }

#pragma unroll 1
    for (int chp = 0; chp < 4; chp++) {
        __syncthreads();
#pragma unroll 4
        for (int k = 0; k < 80; k++) {
            int i = tid + k * 128;
            int c = i & 15;
            int rest = i >> 4;
            int xs = rest % 40;
            int r  = rest / 40;
            int gy = by * 8 + r - 4;
            int gx = bx * 32 + xs - 4;
            float v = 0.f;
            if (gy >= 0 && gy < Hn && gx >= 0 && gx < Wn)
                v = nxt[((size_t)(b * Hn + gy) * Wn + gx) * Cn + chp * 16 + c];
            sbuf[c * 661 + r * 41 + xs] = v;
        }
        __syncthreads();

#pragma unroll 1
        for (int c4 = 0; c4 < 4; c4++) {
            float4 pa = *(const float4*)(prv + pix0 * Cn + chp * 16 + c4 * 4);
            float4 pb = *(const float4*)(prv + pix1 * Cn + chp * 16 + c4 * 4);
            float pav[4] = {pa.x, pa.y, pa.z, pa.w};
            float pbv[4] = {pb.x, pb.y, pb.z, pb.w};
#pragma unroll
            for (int cc = 0; cc < 4; cc++) {
                const float* splane = &sbuf[(c4 * 4 + cc) * 661];
#pragma unroll
                for (int rr = 0; rr < 10; rr++) {
                    const float* q = &splane[(wp * 2 + rr) * 41 + lane + DXB];
#pragma unroll
                    for (int d = 0; d < NDX; d++) {
                        float qv = q[d];
                        if (rr < 9)  acc0[rr * NDX + d]       = fmaf(pav[cc], qv, acc0[rr * NDX + d]);
                        if (rr >= 1) acc1[(rr - 1) * NDX + d] = fmaf(pbv[cc], qv, acc1[(rr - 1) * NDX + d]);
                    }
                }
            }
        }
    }

    __syncthreads();
    const int pl0 = wp * 64 + lane;
#pragma unroll
    for (int t = 0; t < NDX * 9; t++) {
        float v0 = acc0[t] * (1.f / 64.f); v0 = (v0 > 0.f) ? v0 : 0.1f * v0;
        float v1 = acc1[t] * (1.f / 64.f); v1 = (v1 > 0.f) ? v1 : 0.1f * v1;
        sout[t * 257 + pl0]      = v0;
        sout[t * 257 + pl0 + 32] = v1;
    }
    __syncthreads();

    const int TOT = 256 * NDX * 9;
    for (int i = tid; i < TOT; i += 128) {
        int px = i / (NDX * 9);
        int t  = i % (NDX * 9);
        int dy = t / NDX, d = t % NDX;
        int yl = px >> 5, xx = px & 31;
        size_t pix = (size_t)(b * Hn + by * 8 + yl) * Wn + bx * 32 + xx;
        x0[pix * P0 + dy * 9 + DXB + d] = __float2half_rn(sout[t * 257 + px]);
    }

    if (DXB == 0) {
        for (int j = tid; j < 256 * 64; j += 128) {
            int px = j >> 6, c = j & 63;
            int yl = px >> 5, xx = px & 31;
            size_t pix = (size_t)(b * Hn + by * 8 + yl) * Wn + bx * 32 + xx;
            x0[pix * P0 + CV + c]      = __float2half_rn(prv[pix * Cn + c]);
            x0[pix * P0 + CV + 64 + c] = __float2half_rn(nxt[pix * Cn + c]);
            if (c >= 57) x0[pix * P0 + 152 + c] = __float2half_rn(0.f);   // 209..215
        }
    }
}

// ---------------- kernel 2: depthwise 3x3, half4 channels, 4 y-outputs/thread ----------------
template<int QUADS, int STRIDE, int WSTRIDE>
__global__ __launch_bounds__(256, 4)
void dw4y_kernel(const __half* __restrict__ X, const float* __restrict__ Wd,
                 __half* __restrict__ Y)
{
    int idx = blockIdx.x * blockDim.x + threadIdx.x;
    if (idx >= (NPIX / 4) * QUADS) return;
    int q    = idx % QUADS;
    int rest = idx / QUADS;
    int w    = rest % Wn;
    int rest2 = rest / Wn;
    int hg   = rest2 % (Hn / 4);
    int b    = rest2 / (Hn / 4);
    const int h0 = hg * 4;

    float4 wv[9];
#pragma unroll
    for (int t = 0; t < 9; t++)
        wv[t] = *(const float4*)(Wd + t * WSTRIDE + q * 4);

    float4 acc[4];
#pragma unroll
    for (int m = 0; m < 4; m++) acc[m] = make_float4(0.f, 0.f, 0.f, 0.f);

    const bool wl = (w - 1 >= 0), wr = (w + 1 < Wn);

#pragma unroll
    for (int r = 0; r < 6; r++) {            // input rows h0-1 .. h0+4
        int hh = h0 + r - 1;
        if (hh < 0 || hh >= Hn) continue;
        const __half* rowp = X + ((size_t)((b * Hn + hh) * Wn + w)) * STRIDE + q * 4;
#pragma unroll
        for (int kx = 0; kx < 3; kx++) {
            if (kx == 0 && !wl) continue;
            if (kx == 2 && !wr) continue;
            uint2 raw = *(const uint2*)(rowp + (kx - 1) * STRIDE);
            float xv[4];
            h4_to_f(raw, xv);
#pragma unroll
            for (int m = 0; m < 4; m++) {
                int ky = r - m;               // input row = out_y + ky - 1
                if (ky < 0 || ky > 2) continue;
                float4 wq = wv[ky * 3 + kx];
                acc[m].x = fmaf(xv[0], wq.x, acc[m].x);
                acc[m].y = fmaf(xv[1], wq.y, acc[m].y);
                acc[m].z = fmaf(xv[2], wq.z, acc[m].z);
                acc[m].w = fmaf(xv[3], wq.w, acc[m].w);
            }
        }
    }

#pragma unroll
    for (int m = 0; m < 4; m++) {
        size_t pix = (size_t)((b * Hn + h0 + m) * Wn + w);
        *(uint2*)(Y + pix * STRIDE + q * 4) = f_to_h4(acc[m].x, acc[m].y, acc[m].z, acc[m].w);
    }
}

// ---------------- kernel 3: SGEMM (f32x2) + bias + mish, fp16 I/O ----------------
template<int BN_, int TN_, int KTILES>
__global__ __launch_bounds__(256)
void sgemm_mish(const __half* __restrict__ X, int ldX,
                const float* __restrict__ Wp,
                const float* __restrict__ bias,
                __half* __restrict__ Y)
{
    __shared__ float As[2][8][128];
    __shared__ float Bs[2][8][BN_];

    const int tid = threadIdx.x;
    const int px0 = blockIdx.x * 128;

    const int arow = tid >> 1;
    const int acol = (tid & 1) * 4;
    const __half* aptr = X + (size_t)(px0 + arow) * ldX + acol;

    constexpr int BLOADERS = BN_ * 2;
    const int brow = tid / (BN_ / 4);
    const int bcol = (tid % (BN_ / 4)) * 4;
    const float* bptr = Wp + (size_t)brow * BN_ + bcol;

    const int tcx = tid & 15;
    const int tcy = tid >> 4;

    unsigned long long accp[4][TN_];
#pragma unroll
    for (int j = 0; j < 4; j++)
#pragma unroll
        for (int n = 0; n < TN_; n++) accp[j][n] = 0ULL;

    uint2 araw = *(const uint2*)aptr;
    float4 bv;
    if (tid < BLOADERS) bv = *(const float4*)bptr;

    {
        float af[4];
        h4_to_f(araw, af);
        As[0][acol + 0][arow] = af[0];
        As[0][acol + 1][arow] = af[1];
        As[0][acol + 2][arow] = af[2];
        As[0][acol + 3][arow] = af[3];
    }
    if (tid < BLOADERS) *(float4*)&Bs[0][brow][bcol] = bv;
    __syncthreads();

#pragma unroll 1
    for (int kt = 0; kt < KTILES; kt++) {
        const int buf = kt & 1;
        if (kt + 1 < KTILES) {
            araw = *(const uint2*)(aptr + (kt + 1) * 8);
            if (tid < BLOADERS) bv = *(const float4*)(bptr + (size_t)(kt + 1) * 8 * BN_);
        }
#pragma unroll
        for (int kk = 0; kk < 8; kk++) {
            float4 a0 = *(const float4*)&As[buf][kk][tcy * 4];
            float4 a1 = *(const float4*)&As[buf][kk][tcy * 4 + 64];
            unsigned long long ap[4];
            ap[0] = pack2(a0.x, a0.y);
            ap[1] = pack2(a0.z, a0.w);
            ap[2] = pack2(a1.x, a1.y);
            ap[3] = pack2(a1.z, a1.w);

            float br[TN_];
            if constexpr (TN_ == 8) {
                float4 b0 = *(const float4*)&Bs[buf][kk][tcx * 4];
                float4 b1 = *(const float4*)&Bs[buf][kk][tcx * 4 + 64];
                br[0] = b0.x; br[1] = b0.y; br[2] = b0.z; br[3] = b0.w;
                br[4] = b1.x; br[5] = b1.y; br[6] = b1.z; br[7] = b1.w;
            } else if constexpr (TN_ == 4) {
                float4 b0 = *(const float4*)&Bs[buf][kk][tcx * 4];
                br[0] = b0.x; br[1] = b0.y; br[2] = b0.z; br[3] = b0.w;
            } else if constexpr (TN_ == 2) {
                float2 b0 = *(const float2*)&Bs[buf][kk][tcx * 2];
                br[0] = b0.x; br[1] = b0.y;
            } else {
                br[0] = Bs[buf][kk][tcx];
            }
            unsigned long long bd[TN_];
#pragma unroll
            for (int n = 0; n < TN_; n++) bd[n] = pack2(br[n], br[n]);
#pragma unroll
            for (int j = 0; j < 4; j++)
#pragma unroll
                for (int n = 0; n < TN_; n++)
                    ffma2(accp[j][n], ap[j], bd[n]);
        }
        if (kt + 1 < KTILES) {
            const int nb = buf ^ 1;
            float af[4];
            h4_to_f(araw, af);
            As[nb][acol + 0][arow] = af[0];
            As[nb][acol + 1][arow] = af[1];
            As[nb][acol + 2][arow] = af[2];
            As[nb][acol + 3][arow] = af[3];
            if (tid < BLOADERS) *(float4*)&Bs[nb][brow][bcol] = bv;
        }
        __syncthreads();
    }

    float acc[8][TN_];
#pragma unroll
    for (int j = 0; j < 4; j++)
#pragma unroll
        for (int n = 0; n < TN_; n++)
            unpack2(accp[j][n], acc[2 * j][n], acc[2 * j + 1][n]);

    float bb[TN_];
    if constexpr (TN_ == 8) {
        float4 t0 = *(const float4*)&bias[tcx * 4];
        float4 t1 = *(const float4*)&bias[tcx * 4 + 64];
        bb[0]=t0.x; bb[1]=t0.y; bb[2]=t0.z; bb[3]=t0.w;
        bb[4]=t1.x; bb[5]=t1.y; bb[6]=t1.z; bb[7]=t1.w;
    } else if constexpr (TN_ == 4) {
        float4 t0 = *(const float4*)&bias[tcx * 4];
        bb[0]=t0.x; bb[1]=t0.y; bb[2]=t0.z; bb[3]=t0.w;
    } else if constexpr (TN_ == 2) {
        float2 t0 = *(const float2*)&bias[tcx * 2];
        bb[0]=t0.x; bb[1]=t0.y;
    } else {
        bb[0] = bias[tcx];
    }

#pragma unroll
    for (int g = 0; g < 2; g++) {
#pragma unroll
        for (int m = 0; m < 4; m++) {
            int px = px0 + tcy * 4 + m + g * 64;
            __half* yr = Y + (size_t)px * BN_;
            float ov[TN_];
#pragma unroll
            for (int n = 0; n < TN_; n++) ov[n] = mish(acc[g * 4 + m][n] + bb[n]);
            if constexpr (TN_ == 8) {
                *(uint2*)&yr[tcx * 4]      = f_to_h4(ov[0], ov[1], ov[2], ov[3]);
                *(uint2*)&yr[tcx * 4 + 64] = f_to_h4(ov[4], ov[5], ov[6], ov[7]);
            } else if constexpr (TN_ == 4) {
                *(uint2*)&yr[tcx * 4] = f_to_h4(ov[0], ov[1], ov[2], ov[3]);
            } else if constexpr (TN_ == 2) {
                __half2 h = __floats2half2_rn(ov[0], ov[1]);
                *(__half2*)&yr[tcx * 2] = h;
            } else {
                yr[tcx] = __float2half_rn(ov[0]);
            }
        }
    }
}

// ---------------- kernel 4: BN + 3x3 flow conv + scale (smem-tiled) ----------------
// Tile 32x8, halo 1. Stage BN-applied fp32 into [slot][20] (pitch 20 words ->
// conflict-free LDS.128 at lane stride). Zero halo outside image (pad AFTER BN
// per reference: conv pads the BN-ed tensor with zeros).
__global__ __launch_bounds__(256)
void final_kernel(const __half* __restrict__ X,
                  const float* __restrict__ gamma, const float* __restrict__ beta,
                  const float* __restrict__ mean,  const float* __restrict__ var,
                  const float* __restrict__ Wf, float* __restrict__ out)
{
    __shared__ float s[10 * 34 * 20];   // 27.2 KB
    __shared__ float sw[9 * 32];        // flow weights (288 floats)

    const int tid = threadIdx.x;
    const int tx  = tid & 31;
    const int ty  = tid >> 5;
    const int bx = blockIdx.x, by = blockIdx.y, b = blockIdx.z;

    float sc[16], sh[16];
#pragma unroll
    for (int c = 0; c < 16; c++) {
        float scale = gamma[c] * rsqrtf(var[c] + BN_EPS);
        sc[c] = scale;
        sh[c] = beta[c] - mean[c] * scale;
    }
    // FIX (R13 bug): 288 weights > 256 threads -> grid-stride loop
    for (int i = tid; i < 288; i += 256) sw[i] = Wf[i];

    // stage 34x10 slots x 16 ch
    for (int i = tid; i < 34 * 10 * 16; i += 256) {
        int c    = i & 15;
        int slot = i >> 4;
        int xs = slot % 34;
        int ys = slot / 34;
        int gx = bx * 32 + xs - 1;
        int gy = by * 8 + ys - 1;
        float v = 0.f;
        if (gx >= 0 && gx < Wn && gy >= 0 && gy < Hn) {
            float xr = __half2float(X[((size_t)((b * Hn + gy) * Wn + gx)) * 16 + c]);
            v = xr * sc[c] + sh[c];
        }
        s[slot * 20 + c] = v;
    }
    __syncthreads();

    float f0 = 0.f, f1 = 0.f;
#pragma unroll
    for (int dy = 0; dy < 3; dy++) {
#pragma unroll
        for (int dx = 0; dx < 3; dx++) {
            const float* base = &s[((ty + dy) * 34 + (tx + dx)) * 20];
            const float* wr = &sw[(dy * 3 + dx) * 32];
#pragma unroll
            for (int g = 0; g < 4; g++) {
                float4 xv = *(const float4*)(base + g * 4);
                f0 = fmaf(xv.x, wr[(g * 4 + 0) * 2],     f0);
                f1 = fmaf(xv.x, wr[(g * 4 + 0) * 2 + 1], f1);
                f0 = fmaf(xv.y, wr[(g * 4 + 1) * 2],     f0);
                f1 = fmaf(xv.y, wr[(g * 4 + 1) * 2 + 1], f1);
                f0 = fmaf(xv.z, wr[(g * 4 + 2) * 2],     f0);
                f1 = fmaf(xv.z, wr[(g * 4 + 2) * 2 + 1], f1);
                f0 = fmaf(xv.w, wr[(g * 4 + 3) * 2],     f0);
                f1 = fmaf(xv.w, wr[(g * 4 + 3) * 2 + 1], f1);
            }
        }
    }

    size_t pix = (size_t)(b * Hn + by * 8 + ty) * Wn + bx * 32 + tx;
    out[pix * 2 + 0] = FLOW_SCALE * f0;
    out[pix * 2 + 1] = FLOW_SCALE * f1;
}

// ---------------- launch ----------------
extern "C" void kernel_launch(void* const* d_in, const int* in_sizes, int n_in,
                              void* d_out, int out_size)
{
    const float* prv   = (const float*)d_in[0];
    const float* nxt   = (const float*)d_in[1];
    const float* dw0   = (const float*)d_in[2];
    const float* pw0   = (const float*)d_in[3];
    const float* b0    = (const float*)d_in[4];
    const float* dw1   = (const float*)d_in[5];
    const float* pw1   = (const float*)d_in[6];
    const float* b1    = (const float*)d_in[7];
    const float* dw2   = (const float*)d_in[8];
    const float* pw2   = (const float*)d_in[9];
    const float* b2    = (const float*)d_in[10];
    const float* dw3   = (const float*)d_in[11];
    const float* pw3   = (const float*)d_in[12];
    const float* b3    = (const float*)d_in[13];
    const float* bng   = (const float*)d_in[14];
    const float* bnb   = (const float*)d_in[15];
    const float* bnm   = (const float*)d_in[16];
    const float* bnv   = (const float*)d_in[17];
    const float* flw   = (const float*)d_in[18];
    float* out = (float*)d_out;

    __half *A = nullptr, *Bb = nullptr;
    float *W0 = nullptr, *PW0 = nullptr;
    cudaGetSymbolAddress((void**)&A,   g_bufA);
    cudaGetSymbolAddress((void**)&Bb,  g_bufB);
    cudaGetSymbolAddress((void**)&W0,  g_dw0pad);
    cudaGetSymbolAddress((void**)&PW0, g_pw0pad);

    pad_w_kernel<<<(P0 * 128 + 255) / 256, 256>>>(dw0, pw0);

    // cost volume + concat -> A [NPIX, 216] fp16
    {
        dim3 grid(Wn / 32, Hn / 8, Bn);
        cost_kernel<0, 5><<<grid, 128>>>(prv, nxt, A);
        cost_kernel<5, 4><<<grid, 128>>>(prv, nxt, A);
    }

    // layer 0
    dw4y_kernel<54, P0, P0><<<((NPIX / 4) * 54 + 255) / 256, 256>>>(A, W0, Bb);
    sgemm_mish<128, 8, P0 / 8><<<NPIX / 128, 256>>>(Bb, P0, PW0, b0, A);
    // layer 1
    dw4y_kernel<32, 128, 128><<<((NPIX / 4) * 32 + 255) / 256, 256>>>(A, dw1, Bb);
    sgemm_mish<64, 4, 16><<<NPIX / 128, 256>>>(Bb, 128, pw1, b1, A);
    // layer 2
    dw4y_kernel<16, 64, 64><<<((NPIX / 4) * 16 + 255) / 256, 256>>>(A, dw2, Bb);
    sgemm_mish<32, 2, 8><<<NPIX / 128, 256>>>(Bb, 64, pw2, b2, A);
    // layer 3
    dw4y_kernel<8, 32, 32><<<((NPIX / 4) * 8 + 255) / 256, 256>>>(A, dw3, Bb);
    sgemm_mish<16, 1, 4><<<NPIX / 128, 256>>>(Bb, 32, pw3, b3, A);

    // BN + flow conv + scale (tiled)
    {
        dim3 grid(Wn / 32, Hn / 8, Bn);
        final_kernel<<<grid, 256>>>(A, bng, bnb, bnm, bnv, flw, out);
    }
}